// round 1
// baseline (speedup 1.0000x reference)
#include <cuda_runtime.h>
#include <math.h>
#include <stdint.h>

#define N_TOK 8192
#define D_DIM 1024
#define E_NUM 8
#define F_DIM 4096
#define K_CAP 1024

// ---- scratch (device globals: no allocation allowed) ----
__device__ float g_logits[N_TOK * E_NUM];
__device__ float g_probsT[E_NUM * N_TOK];     // expert-major probs
__device__ int   g_sel[E_NUM * K_CAP];
__device__ float g_wts[E_NUM * K_CAP];
__device__ float g_h[(size_t)E_NUM * K_CAP * F_DIM];   // 128 MB intermediate

// ============================================================
// K1: router logits + softmax.  One block per token.
// ============================================================
__global__ void router_kernel(const float* __restrict__ x,
                              const float* __restrict__ rw) {
    int t = blockIdx.x;
    const float* xr = x + (size_t)t * D_DIM;
    float acc[E_NUM];
#pragma unroll
    for (int e = 0; e < E_NUM; e++) acc[e] = 0.0f;
    for (int d = threadIdx.x; d < D_DIM; d += 256) {
        float xv = xr[d];
#pragma unroll
        for (int e = 0; e < E_NUM; e++)
            acc[e] = fmaf(xv, rw[e * D_DIM + d], acc[e]);
    }
    __shared__ float red[E_NUM * 256];
#pragma unroll
    for (int e = 0; e < E_NUM; e++) red[e * 256 + threadIdx.x] = acc[e];
    __syncthreads();
    for (int s = 128; s > 0; s >>= 1) {
        if (threadIdx.x < s) {
#pragma unroll
            for (int e = 0; e < E_NUM; e++)
                red[e * 256 + threadIdx.x] += red[e * 256 + threadIdx.x + s];
        }
        __syncthreads();
    }
    if (threadIdx.x == 0) {
        float l[E_NUM];
        float mx = -1e30f;
#pragma unroll
        for (int e = 0; e < E_NUM; e++) {
            l[e] = red[e * 256];
            g_logits[t * E_NUM + e] = l[e];
            mx = fmaxf(mx, l[e]);
        }
        float s = 0.0f;
#pragma unroll
        for (int e = 0; e < E_NUM; e++) { l[e] = expf(l[e] - mx); s += l[e]; }
        float inv = 1.0f / s;
#pragma unroll
        for (int e = 0; e < E_NUM; e++)
            g_probsT[e * N_TOK + t] = l[e] * inv;
    }
}

// ============================================================
// K2: per-expert top-K via full bitonic sort of 8192 packed keys.
// key = (prob_bits << 32) | (0xFFFFFFFF - idx): descending sort gives
// exactly jax.lax.top_k ordering (value desc, tie -> lower index).
// ============================================================
__global__ void topk_kernel() {
    extern __shared__ unsigned long long key[];
    int e = blockIdx.x;
    const float* p = g_probsT + (size_t)e * N_TOK;
    for (int i = threadIdx.x; i < N_TOK; i += 1024) {
        unsigned fb = __float_as_uint(p[i]);
        key[i] = ((unsigned long long)fb << 32) | (unsigned)(0xFFFFFFFFu - (unsigned)i);
    }
    __syncthreads();
    for (int k = 2; k <= N_TOK; k <<= 1) {
        for (int j = k >> 1; j > 0; j >>= 1) {
            for (int i = threadIdx.x; i < N_TOK; i += 1024) {
                int ixj = i ^ j;
                if (ixj > i) {
                    unsigned long long a = key[i], b = key[ixj];
                    bool desc = ((i & k) == 0);
                    bool swap = desc ? (a < b) : (a > b);
                    if (swap) { key[i] = b; key[ixj] = a; }
                }
            }
            __syncthreads();
        }
    }
    if (threadIdx.x < K_CAP) {
        unsigned long long a = key[threadIdx.x];
        g_wts[e * K_CAP + threadIdx.x] = __uint_as_float((unsigned)(a >> 32));
        g_sel[e * K_CAP + threadIdx.x] = (int)(0xFFFFFFFFu - (unsigned)(a & 0xFFFFFFFFu));
    }
}

// ============================================================
// K3: GEMM1 + bias + exact GELU.  h[e] = gelu(x[sel[e]] @ w1[e] + b1[e])
// 128x128x8 fp32 tile, 8x8 per-thread micro-tile.
// ============================================================
__global__ __launch_bounds__(256, 2) void gemm1_kernel(
    const float* __restrict__ x, const float* __restrict__ w1,
    const float* __restrict__ b1) {
    int e  = blockIdx.z;
    int m0 = blockIdx.y * 128;
    int n0 = blockIdx.x * 128;
    __shared__ float As[8][128];
    __shared__ float Bs[8][128];
    int t = threadIdx.x;
    int arow = t >> 1, acol = (t & 1) * 4;
    int tok = g_sel[e * K_CAP + m0 + arow];
    const float* aptr = x + (size_t)tok * D_DIM + acol;
    int brow = t >> 5, bcol = (t & 31) * 4;
    const float* bptr = w1 + (size_t)e * D_DIM * F_DIM + (size_t)brow * F_DIM + n0 + bcol;
    int mb = (t >> 4) * 8, nb = (t & 15) * 8;
    float acc[8][8];
#pragma unroll
    for (int i = 0; i < 8; i++)
#pragma unroll
        for (int j = 0; j < 8; j++) acc[i][j] = 0.0f;

    for (int k0 = 0; k0 < D_DIM; k0 += 8) {
        float4 av = *(const float4*)(aptr + k0);
        float4 bv = *(const float4*)(bptr + (size_t)k0 * F_DIM);
        As[acol + 0][arow] = av.x; As[acol + 1][arow] = av.y;
        As[acol + 2][arow] = av.z; As[acol + 3][arow] = av.w;
        *(float4*)&Bs[brow][bcol] = bv;
        __syncthreads();
#pragma unroll
        for (int kk = 0; kk < 8; kk++) {
            float a[8], b[8];
            ((float4*)a)[0] = *(const float4*)&As[kk][mb];
            ((float4*)a)[1] = *(const float4*)&As[kk][mb + 4];
            ((float4*)b)[0] = *(const float4*)&Bs[kk][nb];
            ((float4*)b)[1] = *(const float4*)&Bs[kk][nb + 4];
#pragma unroll
            for (int i = 0; i < 8; i++)
#pragma unroll
                for (int j = 0; j < 8; j++)
                    acc[i][j] = fmaf(a[i], b[j], acc[i][j]);
        }
        __syncthreads();
    }
    // epilogue: bias + exact gelu -> g_h
#pragma unroll
    for (int i = 0; i < 8; i++) {
        int gm = m0 + mb + i;
        float* hrow = g_h + ((size_t)e * K_CAP + gm) * F_DIM + n0 + nb;
        float vals[8];
#pragma unroll
        for (int j = 0; j < 8; j++) {
            float c = acc[i][j] + b1[e * F_DIM + n0 + nb + j];
            vals[j] = 0.5f * c * (1.0f + erff(c * 0.70710678118654752f));
        }
        *(float4*)(hrow)     = *(float4*)(vals);
        *(float4*)(hrow + 4) = *(float4*)(vals + 4);
    }
}

// ============================================================
// K4: GEMM2 + bias + combine-weight + scatter-atomicAdd into results.
// ============================================================
__global__ __launch_bounds__(256, 2) void gemm2_kernel(
    const float* __restrict__ w2, const float* __restrict__ b2,
    float* __restrict__ out) {
    int e  = blockIdx.z;
    int m0 = blockIdx.y * 128;
    int n0 = blockIdx.x * 128;
    __shared__ float As[8][128];
    __shared__ float Bs[8][128];
    int t = threadIdx.x;
    int arow = t >> 1, acol = (t & 1) * 4;
    const float* aptr = g_h + ((size_t)e * K_CAP + m0 + arow) * F_DIM + acol;
    int brow = t >> 5, bcol = (t & 31) * 4;
    const float* bptr = w2 + (size_t)e * F_DIM * D_DIM + (size_t)brow * D_DIM + n0 + bcol;
    int mb = (t >> 4) * 8, nb = (t & 15) * 8;
    float acc[8][8];
#pragma unroll
    for (int i = 0; i < 8; i++)
#pragma unroll
        for (int j = 0; j < 8; j++) acc[i][j] = 0.0f;

    for (int k0 = 0; k0 < F_DIM; k0 += 8) {
        float4 av = *(const float4*)(aptr + k0);
        float4 bv = *(const float4*)(bptr + (size_t)k0 * D_DIM);
        As[acol + 0][arow] = av.x; As[acol + 1][arow] = av.y;
        As[acol + 2][arow] = av.z; As[acol + 3][arow] = av.w;
        *(float4*)&Bs[brow][bcol] = bv;
        __syncthreads();
#pragma unroll
        for (int kk = 0; kk < 8; kk++) {
            float a[8], b[8];
            ((float4*)a)[0] = *(const float4*)&As[kk][mb];
            ((float4*)a)[1] = *(const float4*)&As[kk][mb + 4];
            ((float4*)b)[0] = *(const float4*)&Bs[kk][nb];
            ((float4*)b)[1] = *(const float4*)&Bs[kk][nb + 4];
#pragma unroll
            for (int i = 0; i < 8; i++)
#pragma unroll
                for (int j = 0; j < 8; j++)
                    acc[i][j] = fmaf(a[i], b[j], acc[i][j]);
        }
        __syncthreads();
    }
#pragma unroll
    for (int i = 0; i < 8; i++) {
        int gm  = m0 + mb + i;
        int tok = g_sel[e * K_CAP + gm];
        float w = g_wts[e * K_CAP + gm];
        float* orow = out + (size_t)tok * D_DIM + n0 + nb;
#pragma unroll
        for (int j = 0; j < 8; j++) {
            float v = (acc[i][j] + b2[e * D_DIM + n0 + nb + j]) * w;
            atomicAdd(orow + j, v);
        }
    }
}

// ============================================================
// K5: optional extra outputs (router_logits, selected_tokens as float)
// ============================================================
__global__ void tail_kernel(float* __restrict__ out, int mode) {
    int i = blockIdx.x * 256 + threadIdx.x;
    const int R = N_TOK * D_DIM;
    if (mode >= 1 && i < N_TOK * E_NUM) out[R + i] = g_logits[i];
    if (mode >= 2 && i < E_NUM * K_CAP) out[R + N_TOK * E_NUM + i] = (float)g_sel[i];
}

extern "C" void kernel_launch(void* const* d_in, const int* in_sizes, int n_in,
                              void* d_out, int out_size) {
    const float* x  = (const float*)d_in[0];
    const float* rw = (const float*)d_in[1];
    const float* w1 = (const float*)d_in[2];
    const float* b1 = (const float*)d_in[3];
    const float* w2 = (const float*)d_in[4];
    const float* b2 = (const float*)d_in[5];
    float* out = (float*)d_out;

    // results region must start from zero (d_out is poisoned)
    cudaMemsetAsync(out, 0, (size_t)N_TOK * D_DIM * sizeof(float), 0);

    router_kernel<<<N_TOK, 256>>>(x, rw);

    cudaFuncSetAttribute(topk_kernel, cudaFuncAttributeMaxDynamicSharedMemorySize,
                         N_TOK * sizeof(unsigned long long));
    topk_kernel<<<E_NUM, 1024, N_TOK * sizeof(unsigned long long)>>>();

    gemm1_kernel<<<dim3(F_DIM / 128, K_CAP / 128, E_NUM), 256>>>(x, w1, b1);
    gemm2_kernel<<<dim3(D_DIM / 128, K_CAP / 128, E_NUM), 256>>>(w2, b2, out);

    const int R = N_TOK * D_DIM;                 // 8388608
    if (out_size >= R + N_TOK * E_NUM) {
        int mode = (out_size >= R + N_TOK * E_NUM + E_NUM * K_CAP) ? 2 : 1;
        tail_kernel<<<(N_TOK * E_NUM + 255) / 256, 256>>>(out, mode);
    }
}

// round 7
// speedup vs baseline: 2.8378x; 2.8378x over previous
#include <cuda_runtime.h>
#include <math.h>
#include <stdint.h>

#define N_TOK 8192
#define D_DIM 1024
#define E_NUM 8
#define F_DIM 4096
#define K_CAP 1024

// ---- scratch (device globals: no allocation allowed) ----
__device__ float g_logits[N_TOK * E_NUM];
__device__ float g_probsT[E_NUM * N_TOK];
__device__ int   g_sel[E_NUM * K_CAP];
__device__ float g_wts[E_NUM * K_CAP];
__device__ float g_h[(size_t)E_NUM * K_CAP * F_DIM];   // 128 MB intermediate

// ============================================================ helpers
__device__ __forceinline__ void cp16(uint32_t dst, const void* src) {
    asm volatile("cp.async.cg.shared.global [%0], [%1], 16;" :: "r"(dst), "l"(src));
}
__device__ __forceinline__ uint32_t smem_u32(const void* p) {
    uint32_t a;
    asm("{ .reg .u64 t; cvta.to.shared.u64 t, %1; cvt.u32.u64 %0, t; }"
        : "=r"(a) : "l"(p));
    return a;
}
__device__ __forceinline__ uint32_t f2tf(float f) {
    uint32_t u; asm("cvt.rna.tf32.f32 %0, %1;" : "=r"(u) : "f"(f)); return u;
}
__device__ __forceinline__ void mma1688(float* c, const uint32_t* a, const uint32_t* b) {
    asm volatile(
        "mma.sync.aligned.m16n8k8.row.col.f32.tf32.tf32.f32 "
        "{%0,%1,%2,%3}, {%4,%5,%6,%7}, {%8,%9}, {%0,%1,%2,%3};"
        : "+f"(c[0]), "+f"(c[1]), "+f"(c[2]), "+f"(c[3])
        : "r"(a[0]), "r"(a[1]), "r"(a[2]), "r"(a[3]), "r"(b[0]), "r"(b[1]));
}

// ============================================================
// K1: router logits + softmax (one block per token)
// ============================================================
__global__ void router_kernel(const float* __restrict__ x,
                              const float* __restrict__ rw) {
    int t = blockIdx.x;
    const float* xr = x + (size_t)t * D_DIM;
    float acc[E_NUM];
#pragma unroll
    for (int e = 0; e < E_NUM; e++) acc[e] = 0.0f;
    for (int d = threadIdx.x; d < D_DIM; d += 256) {
        float xv = xr[d];
#pragma unroll
        for (int e = 0; e < E_NUM; e++)
            acc[e] = fmaf(xv, rw[e * D_DIM + d], acc[e]);
    }
    __shared__ float red[E_NUM * 256];
#pragma unroll
    for (int e = 0; e < E_NUM; e++) red[e * 256 + threadIdx.x] = acc[e];
    __syncthreads();
    for (int s = 128; s > 0; s >>= 1) {
        if (threadIdx.x < s) {
#pragma unroll
            for (int e = 0; e < E_NUM; e++)
                red[e * 256 + threadIdx.x] += red[e * 256 + threadIdx.x + s];
        }
        __syncthreads();
    }
    if (threadIdx.x == 0) {
        float l[E_NUM];
        float mx = -1e30f;
#pragma unroll
        for (int e = 0; e < E_NUM; e++) {
            l[e] = red[e * 256];
            g_logits[t * E_NUM + e] = l[e];
            mx = fmaxf(mx, l[e]);
        }
        float s = 0.0f;
#pragma unroll
        for (int e = 0; e < E_NUM; e++) { l[e] = expf(l[e] - mx); s += l[e]; }
        float inv = 1.0f / s;
#pragma unroll
        for (int e = 0; e < E_NUM; e++)
            g_probsT[e * N_TOK + t] = l[e] * inv;
    }
}

// ============================================================
// K2: per-expert top-K via bitonic sort of 8192 packed keys
// ============================================================
__global__ void topk_kernel() {
    extern __shared__ unsigned long long key[];
    int e = blockIdx.x;
    const float* p = g_probsT + (size_t)e * N_TOK;
    for (int i = threadIdx.x; i < N_TOK; i += 1024) {
        unsigned fb = __float_as_uint(p[i]);
        key[i] = ((unsigned long long)fb << 32) | (unsigned)(0xFFFFFFFFu - (unsigned)i);
    }
    __syncthreads();
    for (int k = 2; k <= N_TOK; k <<= 1) {
        for (int j = k >> 1; j > 0; j >>= 1) {
            for (int i = threadIdx.x; i < N_TOK; i += 1024) {
                int ixj = i ^ j;
                if (ixj > i) {
                    unsigned long long a = key[i], b = key[ixj];
                    bool desc = ((i & k) == 0);
                    bool swap = desc ? (a < b) : (a > b);
                    if (swap) { key[i] = b; key[ixj] = a; }
                }
            }
            __syncthreads();
        }
    }
    if (threadIdx.x < K_CAP) {
        unsigned long long a = key[threadIdx.x];
        g_wts[e * K_CAP + threadIdx.x] = __uint_as_float((unsigned)(a >> 32));
        g_sel[e * K_CAP + threadIdx.x] = (int)(0xFFFFFFFFu - (unsigned)(a & 0xFFFFFFFFu));
    }
}

// ============================================================
// tf32 mma.sync GEMM: CTA tile 128x128, warp tile 64x32 (2x4 warps),
// k-tile 16, 4-stage cp.async pipeline.
// A is [rows, KDIM] k-contiguous (gathered via g_sel if IS_G1).
// B is [KDIM, NDIM] n-contiguous (native w1/w2 layout).
// ============================================================
#define A_STRIDE 20                      // floats per A smem row (pad 16->20)
#define B_STRIDE 136                     // floats per B smem row (pad 128->136)
#define A_SZ (128 * A_STRIDE * 4)        // 10240 B
#define B_SZ (16 * B_STRIDE * 4)         // 8704 B
#define STG_SZ (A_SZ + B_SZ)             // 18944 B
#define NSTAGE 4
#define SMEM_DYN (NSTAGE * STG_SZ)       // 75776 B

template <int KDIM, int NDIM, bool IS_G1>
__global__ __launch_bounds__(256, 2) void moe_gemm_kernel(
    const float* __restrict__ A_src, const float* __restrict__ B_src,
    const float* __restrict__ bias, float* __restrict__ out) {
    constexpr int KT = KDIM / 16;

    extern __shared__ char smem[];
    uint32_t sb = smem_u32(smem);
    float* sm = (float*)smem;

    int e = blockIdx.z, m0 = blockIdx.y * 128, n0 = blockIdx.x * 128;
    int t = threadIdx.x, wid = t >> 5, lane = t & 31;
    int wm = (wid >> 2) * 64, wn = (wid & 3) * 32;

    // ---- cp.async source pointers (fixed; advance by k-tile) ----
    int rA = t >> 2, kcA = t & 3;          // A: 2 chunks (rows rA, rA+64)
    int krB = t >> 5, ncB = t & 31;        // B: 2 chunks (k rows krB, krB+8)
    const float *as0, *as1;
    if (IS_G1) {
        as0 = A_src + (size_t)g_sel[e * K_CAP + m0 + rA] * KDIM + kcA * 4;
        as1 = A_src + (size_t)g_sel[e * K_CAP + m0 + rA + 64] * KDIM + kcA * 4;
    } else {
        as0 = A_src + ((size_t)e * K_CAP + m0 + rA) * KDIM + kcA * 4;
        as1 = as0 + (size_t)64 * KDIM;
    }
    const float* bs0 = B_src + (size_t)e * KDIM * NDIM + (size_t)krB * NDIM + n0 + ncB * 4;
    const float* bs1 = bs0 + (size_t)8 * NDIM;
    uint32_t adst0 = sb + rA * (A_STRIDE * 4) + kcA * 16;
    uint32_t adst1 = sb + (rA + 64) * (A_STRIDE * 4) + kcA * 16;
    uint32_t bdst0 = sb + A_SZ + krB * (B_STRIDE * 4) + ncB * 16;
    uint32_t bdst1 = sb + A_SZ + (krB + 8) * (B_STRIDE * 4) + ncB * 16;

#define LOAD_STAGE(SLOT, KTILE)                                                 \
    do {                                                                        \
        uint32_t off = (uint32_t)(SLOT) * STG_SZ;                               \
        size_t ka = (size_t)(KTILE) * 16;                                       \
        size_t kb = (size_t)(KTILE) * 16 * NDIM;                                \
        cp16(adst0 + off, as0 + ka);                                            \
        cp16(adst1 + off, as1 + ka);                                            \
        cp16(bdst0 + off, bs0 + kb);                                            \
        cp16(bdst1 + off, bs1 + kb);                                            \
        asm volatile("cp.async.commit_group;");                                 \
    } while (0)

    float acc[4][4][4];
#pragma unroll
    for (int mi = 0; mi < 4; mi++)
#pragma unroll
        for (int ni = 0; ni < 4; ni++)
#pragma unroll
            for (int r = 0; r < 4; r++) acc[mi][ni][r] = 0.0f;

    LOAD_STAGE(0, 0); LOAD_STAGE(1, 1); LOAD_STAGE(2, 2);

    int lg = lane >> 2, lt = lane & 3;

#pragma unroll 1
    for (int kt = 0; kt < KT; kt++) {
        int rem = KT - 1 - kt;
        if (rem >= 2)      asm volatile("cp.async.wait_group 2;");
        else if (rem == 1) asm volatile("cp.async.wait_group 1;");
        else               asm volatile("cp.async.wait_group 0;");
        __syncthreads();
        if (kt + 3 < KT) LOAD_STAGE((kt + 3) & (NSTAGE - 1), kt + 3);

        const float* As = sm + (size_t)(kt & (NSTAGE - 1)) * (STG_SZ / 4);
        const float* Bs = As + A_SZ / 4;

#pragma unroll
        for (int s8 = 0; s8 < 2; s8++) {
            int kk = s8 * 8 + lt;
            uint32_t af[4][4], bf[4][2];
#pragma unroll
            for (int mi = 0; mi < 4; mi++) {
                int row = wm + mi * 16 + lg;
                af[mi][0] = f2tf(As[row * A_STRIDE + kk]);
                af[mi][1] = f2tf(As[(row + 8) * A_STRIDE + kk]);
                af[mi][2] = f2tf(As[row * A_STRIDE + kk + 4]);
                af[mi][3] = f2tf(As[(row + 8) * A_STRIDE + kk + 4]);
            }
#pragma unroll
            for (int ni = 0; ni < 4; ni++) {
                int col = wn + ni * 8 + lg;
                bf[ni][0] = f2tf(Bs[kk * B_STRIDE + col]);
                bf[ni][1] = f2tf(Bs[(kk + 4) * B_STRIDE + col]);
            }
#pragma unroll
            for (int mi = 0; mi < 4; mi++)
#pragma unroll
                for (int ni = 0; ni < 4; ni++)
                    mma1688(acc[mi][ni], af[mi], bf[ni]);
        }
    }
#undef LOAD_STAGE

    // ---- epilogue ----
    // C frag: c0,c1 -> (row lg,   col 2*lt, 2*lt+1)
    //         c2,c3 -> (row lg+8, same cols)
    if (IS_G1) {
#pragma unroll
        for (int mi = 0; mi < 4; mi++) {
            int m = m0 + wm + mi * 16 + lg;
#pragma unroll
            for (int ni = 0; ni < 4; ni++) {
                int n = n0 + wn + ni * 8 + 2 * lt;
                float b0 = bias[(size_t)e * NDIM + n];
                float b1v = bias[(size_t)e * NDIM + n + 1];
#pragma unroll
                for (int half = 0; half < 2; half++) {
                    int mm = m + half * 8;
                    float v0 = acc[mi][ni][half * 2 + 0] + b0;
                    float v1 = acc[mi][ni][half * 2 + 1] + b1v;
                    v0 = 0.5f * v0 * (1.0f + erff(v0 * 0.70710678118654752f));
                    v1 = 0.5f * v1 * (1.0f + erff(v1 * 0.70710678118654752f));
                    float2 v = make_float2(v0, v1);
                    *(float2*)(out + ((size_t)e * K_CAP + mm) * F_DIM + n) = v;
                }
            }
        }
    } else {
#pragma unroll
        for (int mi = 0; mi < 4; mi++) {
            int m = m0 + wm + mi * 16 + lg;
            int tok0 = g_sel[e * K_CAP + m];
            int tok1 = g_sel[e * K_CAP + m + 8];
            float w0 = g_wts[e * K_CAP + m];
            float w1v = g_wts[e * K_CAP + m + 8];
#pragma unroll
            for (int ni = 0; ni < 4; ni++) {
                int n = n0 + wn + ni * 8 + 2 * lt;
                float b0 = bias[(size_t)e * NDIM + n];
                float b1v = bias[(size_t)e * NDIM + n + 1];
                atomicAdd(out + (size_t)tok0 * D_DIM + n,     (acc[mi][ni][0] + b0) * w0);
                atomicAdd(out + (size_t)tok0 * D_DIM + n + 1, (acc[mi][ni][1] + b1v) * w0);
                atomicAdd(out + (size_t)tok1 * D_DIM + n,     (acc[mi][ni][2] + b0) * w1v);
                atomicAdd(out + (size_t)tok1 * D_DIM + n + 1, (acc[mi][ni][3] + b1v) * w1v);
            }
        }
    }
}

// ============================================================
// K5: optional extra outputs
// ============================================================
__global__ void tail_kernel(float* __restrict__ out, int mode) {
    int i = blockIdx.x * 256 + threadIdx.x;
    const int R = N_TOK * D_DIM;
    if (mode >= 1 && i < N_TOK * E_NUM) out[R + i] = g_logits[i];
    if (mode >= 2 && i < E_NUM * K_CAP) out[R + N_TOK * E_NUM + i] = (float)g_sel[i];
}

extern "C" void kernel_launch(void* const* d_in, const int* in_sizes, int n_in,
                              void* d_out, int out_size) {
    const float* x  = (const float*)d_in[0];
    const float* rw = (const float*)d_in[1];
    const float* w1 = (const float*)d_in[2];
    const float* b1 = (const float*)d_in[3];
    const float* w2 = (const float*)d_in[4];
    const float* b2 = (const float*)d_in[5];
    float* out = (float*)d_out;

    cudaMemsetAsync(out, 0, (size_t)N_TOK * D_DIM * sizeof(float), 0);

    router_kernel<<<N_TOK, 256>>>(x, rw);

    cudaFuncSetAttribute(topk_kernel, cudaFuncAttributeMaxDynamicSharedMemorySize,
                         N_TOK * sizeof(unsigned long long));
    topk_kernel<<<E_NUM, 1024, N_TOK * sizeof(unsigned long long)>>>();

    float* h; cudaGetSymbolAddress((void**)&h, g_h);

    cudaFuncSetAttribute((const void*)moe_gemm_kernel<D_DIM, F_DIM, true>,
                         cudaFuncAttributeMaxDynamicSharedMemorySize, SMEM_DYN);
    cudaFuncSetAttribute((const void*)moe_gemm_kernel<F_DIM, D_DIM, false>,
                         cudaFuncAttributeMaxDynamicSharedMemorySize, SMEM_DYN);

    // GEMM1: h = gelu(gather(x) @ w1 + b1)
    moe_gemm_kernel<D_DIM, F_DIM, true>
        <<<dim3(F_DIM / 128, K_CAP / 128, E_NUM), 256, SMEM_DYN>>>(x, w1, b1, h);
    // GEMM2: out += scatter((h @ w2 + b2) * wts)
    moe_gemm_kernel<F_DIM, D_DIM, false>
        <<<dim3(D_DIM / 128, K_CAP / 128, E_NUM), 256, SMEM_DYN>>>(h, w2, b2, out);

    const int R = N_TOK * D_DIM;
    if (out_size >= R + N_TOK * E_NUM) {
        int mode = (out_size >= R + N_TOK * E_NUM + E_NUM * K_CAP) ? 2 : 1;
        tail_kernel<<<(N_TOK * E_NUM + 255) / 256, 256>>>(out, mode);
    }
}

// round 9
// speedup vs baseline: 3.1139x; 1.0973x over previous
#include <cuda_runtime.h>
#include <math.h>
#include <stdint.h>

#define N_TOK 8192
#define D_DIM 1024
#define E_NUM 8
#define F_DIM 4096
#define K_CAP 1024

// ---- scratch (device globals: no allocation allowed) ----
__device__ float g_logits[N_TOK * E_NUM];
__device__ float g_probsT[E_NUM * N_TOK];
__device__ int   g_sel[E_NUM * K_CAP];
__device__ float g_wts[E_NUM * K_CAP];
__device__ float g_h  [(size_t)E_NUM * K_CAP * F_DIM];   // 128 MB (tf32-rounded)
__device__ float g_xr [(size_t)N_TOK * D_DIM];           // 32 MB
__device__ float g_w1r[(size_t)E_NUM * D_DIM * F_DIM];   // 128 MB
__device__ float g_w2r[(size_t)E_NUM * F_DIM * D_DIM];   // 128 MB

// ============================================================ helpers
__device__ __forceinline__ void cp16(uint32_t dst, const void* src) {
    asm volatile("cp.async.cg.shared.global [%0], [%1], 16;" :: "r"(dst), "l"(src));
}
__device__ __forceinline__ uint32_t smem_u32(const void* p) {
    uint32_t a;
    asm("{ .reg .u64 t; cvta.to.shared.u64 t, %1; cvt.u32.u64 %0, t; }"
        : "=r"(a) : "l"(p));
    return a;
}
__device__ __forceinline__ float to_tf32(float f) {
    float r; asm("cvt.rna.tf32.f32 %0, %1;" : "=f"(r) : "f"(f)); return r;
}
__device__ __forceinline__ void mma1688(float* c, const uint32_t* a, const uint32_t* b) {
    asm volatile(
        "mma.sync.aligned.m16n8k8.row.col.f32.tf32.tf32.f32 "
        "{%0,%1,%2,%3}, {%4,%5,%6,%7}, {%8,%9}, {%0,%1,%2,%3};"
        : "+f"(c[0]), "+f"(c[1]), "+f"(c[2]), "+f"(c[3])
        : "r"(a[0]), "r"(a[1]), "r"(a[2]), "r"(a[3]), "r"(b[0]), "r"(b[1]));
}

// ============================================================
// K0: elementwise tf32 rounding (grid-stride float4)
// ============================================================
__global__ void cvt_round_kernel(const float* __restrict__ src,
                                 float* __restrict__ dst, size_t n4) {
    size_t stride = (size_t)gridDim.x * blockDim.x;
    for (size_t i = (size_t)blockIdx.x * blockDim.x + threadIdx.x; i < n4; i += stride) {
        float4 v = ((const float4*)src)[i];
        v.x = to_tf32(v.x); v.y = to_tf32(v.y);
        v.z = to_tf32(v.z); v.w = to_tf32(v.w);
        ((float4*)dst)[i] = v;
    }
}

// ============================================================
// K1: router logits + softmax (one block per token)
// ============================================================
__global__ void router_kernel(const float* __restrict__ x,
                              const float* __restrict__ rw) {
    int t = blockIdx.x;
    const float* xr = x + (size_t)t * D_DIM;
    float acc[E_NUM];
#pragma unroll
    for (int e = 0; e < E_NUM; e++) acc[e] = 0.0f;
    for (int d = threadIdx.x; d < D_DIM; d += 256) {
        float xv = xr[d];
#pragma unroll
        for (int e = 0; e < E_NUM; e++)
            acc[e] = fmaf(xv, rw[e * D_DIM + d], acc[e]);
    }
    __shared__ float red[E_NUM * 256];
#pragma unroll
    for (int e = 0; e < E_NUM; e++) red[e * 256 + threadIdx.x] = acc[e];
    __syncthreads();
    for (int s = 128; s > 0; s >>= 1) {
        if (threadIdx.x < s) {
#pragma unroll
            for (int e = 0; e < E_NUM; e++)
                red[e * 256 + threadIdx.x] += red[e * 256 + threadIdx.x + s];
        }
        __syncthreads();
    }
    if (threadIdx.x == 0) {
        float l[E_NUM];
        float mx = -1e30f;
#pragma unroll
        for (int e = 0; e < E_NUM; e++) {
            l[e] = red[e * 256];
            g_logits[t * E_NUM + e] = l[e];
            mx = fmaxf(mx, l[e]);
        }
        float s = 0.0f;
#pragma unroll
        for (int e = 0; e < E_NUM; e++) { l[e] = expf(l[e] - mx); s += l[e]; }
        float inv = 1.0f / s;
#pragma unroll
        for (int e = 0; e < E_NUM; e++)
            g_probsT[e * N_TOK + t] = l[e] * inv;
    }
}

// ============================================================
// K2: per-expert top-K via radix-select + small bitonic of winners.
// Selection set & order identical to jax.lax.top_k: 64-bit packed key
// (prob_bits<<32)|(~idx) -> value desc, tie -> lower idx. Distinct keys.
// ============================================================
#define TOPK_BINS 4096
__global__ void topk_select_kernel() {
    extern __shared__ unsigned long long cand[];         // dyn, N_TOK entries
    __shared__ unsigned hist[TOPK_BINS];
    __shared__ unsigned suf[1024];
    __shared__ unsigned long long outk[K_CAP];
    __shared__ unsigned s_binB, s_need, s_ncand, s_slot, s_coarse;

    int e = blockIdx.x, tid = threadIdx.x;
    const float* p = g_probsT + (size_t)e * N_TOK;

#pragma unroll
    for (int i = 0; i < TOPK_BINS / 1024; i++) hist[tid + i * 1024] = 0;
    if (tid == 0) { s_ncand = 0; s_slot = 0; s_coarse = 0; }
    __syncthreads();

    unsigned fb[8];
#pragma unroll
    for (int k = 0; k < 8; k++) {
        int i = tid + k * 1024;
        fb[k] = __float_as_uint(p[i]);
        atomicAdd(&hist[fb[k] >> 20], 1u);
    }
    __syncthreads();

    // coarse suffix sums: thread t covers bins [4t, 4t+4)
    unsigned s = hist[4 * tid] + hist[4 * tid + 1] + hist[4 * tid + 2] + hist[4 * tid + 3];
    suf[tid] = s;
    __syncthreads();
    for (int off = 1; off < 1024; off <<= 1) {
        unsigned v = (tid + off < 1024) ? suf[tid + off] : 0;
        __syncthreads();
        suf[tid] += v;
        __syncthreads();
    }
    // unique coarse t*: suf[t*] >= K > suf[t*+1]
    if (suf[tid] >= K_CAP && (tid == 1023 || suf[tid + 1] < K_CAP)) s_coarse = tid;
    __syncthreads();
    if (tid == 0) {
        unsigned co = s_coarse;
        unsigned above = (co == 1023) ? 0 : suf[co + 1];
        unsigned B = 4 * co, need = 0;
        for (int b = 4 * (int)co + 3; b >= 4 * (int)co; b--) {
            if (above + hist[b] >= K_CAP) { B = (unsigned)b; need = K_CAP - above; break; }
            above += hist[b];
        }
        s_binB = B; s_need = need;
    }
    __syncthreads();
    unsigned B = s_binB, need = s_need;

    // emit bins > B directly; collect bin == B candidates
#pragma unroll
    for (int k = 0; k < 8; k++) {
        int i = tid + k * 1024;
        unsigned b = fb[k] >> 20;
        unsigned long long key =
            ((unsigned long long)fb[k] << 32) | (unsigned)(0xFFFFFFFFu - (unsigned)i);
        if (b > B) {
            unsigned sl = atomicAdd(&s_slot, 1u);
            outk[sl] = key;
        } else if (b == B) {
            unsigned c = atomicAdd(&s_ncand, 1u);
            cand[c] = key;
        }
    }
    __syncthreads();
    unsigned c = s_ncand;
    for (unsigned j = tid; j < c; j += 1024) {
        unsigned long long kj = cand[j];
        unsigned rank = 0;
        for (unsigned l = 0; l < c; l++) rank += (cand[l] > kj);
        if (rank < need) {
            unsigned sl = atomicAdd(&s_slot, 1u);
            outk[sl] = kj;
        }
    }
    __syncthreads();

    // bitonic sort 1024 winners descending (restores reference slot order)
    for (int k = 2; k <= K_CAP; k <<= 1) {
        for (int j = k >> 1; j > 0; j >>= 1) {
            int ixj = tid ^ j;
            if (ixj > tid) {
                unsigned long long a = outk[tid], bk = outk[ixj];
                bool desc = ((tid & k) == 0);
                if (desc ? (a < bk) : (a > bk)) { outk[tid] = bk; outk[ixj] = a; }
            }
            __syncthreads();
        }
    }
    unsigned long long a = outk[tid];
    g_wts[e * K_CAP + tid] = __uint_as_float((unsigned)(a >> 32));
    g_sel[e * K_CAP + tid] = (int)(0xFFFFFFFFu - (unsigned)(a & 0xFFFFFFFFu));
}

// ============================================================
// tf32 mma.sync GEMM: CTA 128x128, warp 64x32 (2x4 warps),
// k-tile 16, 5-stage cp.async pipeline. Inputs pre-rounded to tf32:
// mainloop has ZERO cvt instructions (raw-bit fragments).
// ============================================================
#define A_STRIDE 20
#define B_STRIDE 136
#define A_SZ (128 * A_STRIDE * 4)        // 10240 B
#define B_SZ (16 * B_STRIDE * 4)         // 8704 B
#define STG_SZ (A_SZ + B_SZ)             // 18944 B
#define NSTAGE 5
#define SMEM_DYN (NSTAGE * STG_SZ)       // 94720 B

template <int KDIM, int NDIM, bool IS_G1>
__global__ __launch_bounds__(256, 2) void moe_gemm_kernel(
    const float* __restrict__ A_src, const float* __restrict__ B_src,
    const float* __restrict__ bias, float* __restrict__ out) {
    constexpr int KT = KDIM / 16;

    extern __shared__ char smem[];
    uint32_t sb = smem_u32(smem);
    const uint32_t* smu = (const uint32_t*)smem;

    int e = blockIdx.z, m0 = blockIdx.y * 128, n0 = blockIdx.x * 128;
    int t = threadIdx.x, wid = t >> 5, lane = t & 31;
    int wm = (wid >> 2) * 64, wn = (wid & 3) * 32;

    int rA = t >> 2, kcA = t & 3;
    int krB = t >> 5, ncB = t & 31;
    const float *as0, *as1;
    if (IS_G1) {
        as0 = A_src + (size_t)g_sel[e * K_CAP + m0 + rA] * KDIM + kcA * 4;
        as1 = A_src + (size_t)g_sel[e * K_CAP + m0 + rA + 64] * KDIM + kcA * 4;
    } else {
        as0 = A_src + ((size_t)e * K_CAP + m0 + rA) * KDIM + kcA * 4;
        as1 = as0 + (size_t)64 * KDIM;
    }
    const float* bs0 = B_src + (size_t)e * KDIM * NDIM + (size_t)krB * NDIM + n0 + ncB * 4;
    const float* bs1 = bs0 + (size_t)8 * NDIM;
    uint32_t adst0 = sb + rA * (A_STRIDE * 4) + kcA * 16;
    uint32_t adst1 = sb + (rA + 64) * (A_STRIDE * 4) + kcA * 16;
    uint32_t bdst0 = sb + A_SZ + krB * (B_STRIDE * 4) + ncB * 16;
    uint32_t bdst1 = sb + A_SZ + (krB + 8) * (B_STRIDE * 4) + ncB * 16;

#define LOAD_STAGE(SLOT, KTILE)                                                 \
    do {                                                                        \
        uint32_t off = (uint32_t)(SLOT) * STG_SZ;                               \
        size_t ka = (size_t)(KTILE) * 16;                                       \
        size_t kb = (size_t)(KTILE) * 16 * NDIM;                                \
        cp16(adst0 + off, as0 + ka);                                            \
        cp16(adst1 + off, as1 + ka);                                            \
        cp16(bdst0 + off, bs0 + kb);                                            \
        cp16(bdst1 + off, bs1 + kb);                                            \
        asm volatile("cp.async.commit_group;");                                 \
    } while (0)

    float acc[4][4][4];
#pragma unroll
    for (int mi = 0; mi < 4; mi++)
#pragma unroll
        for (int ni = 0; ni < 4; ni++)
#pragma unroll
            for (int r = 0; r < 4; r++) acc[mi][ni][r] = 0.0f;

    LOAD_STAGE(0, 0); LOAD_STAGE(1, 1); LOAD_STAGE(2, 2); LOAD_STAGE(3, 3);

    int lg = lane >> 2, lt = lane & 3;
    int cur = 0, nxt = NSTAGE - 1;

#pragma unroll 1
    for (int kt = 0; kt < KT; kt++) {
        int rem = KT - 1 - kt;
        if (rem >= 3)      asm volatile("cp.async.wait_group 3;");
        else if (rem == 2) asm volatile("cp.async.wait_group 2;");
        else if (rem == 1) asm volatile("cp.async.wait_group 1;");
        else               asm volatile("cp.async.wait_group 0;");
        __syncthreads();
        if (kt + NSTAGE - 1 < KT) LOAD_STAGE(nxt, kt + NSTAGE - 1);

        const uint32_t* As = smu + (size_t)cur * (STG_SZ / 4);
        const uint32_t* Bs = As + A_SZ / 4;

#pragma unroll
        for (int s8 = 0; s8 < 2; s8++) {
            int kk = s8 * 8 + lt;
            uint32_t af[4][4], bf[4][2];
#pragma unroll
            for (int mi = 0; mi < 4; mi++) {
                int row = wm + mi * 16 + lg;
                af[mi][0] = As[row * A_STRIDE + kk];
                af[mi][1] = As[(row + 8) * A_STRIDE + kk];
                af[mi][2] = As[row * A_STRIDE + kk + 4];
                af[mi][3] = As[(row + 8) * A_STRIDE + kk + 4];
            }
#pragma unroll
            for (int ni = 0; ni < 4; ni++) {
                int col = wn + ni * 8 + lg;
                bf[ni][0] = Bs[kk * B_STRIDE + col];
                bf[ni][1] = Bs[(kk + 4) * B_STRIDE + col];
            }
#pragma unroll
            for (int mi = 0; mi < 4; mi++)
#pragma unroll
                for (int ni = 0; ni < 4; ni++)
                    mma1688(acc[mi][ni], af[mi], bf[ni]);
        }
        cur = (cur + 1 == NSTAGE) ? 0 : cur + 1;
        nxt = (nxt + 1 == NSTAGE) ? 0 : nxt + 1;
    }
#undef LOAD_STAGE

    // ---- epilogue ----
    if (IS_G1) {
#pragma unroll
        for (int mi = 0; mi < 4; mi++) {
            int m = m0 + wm + mi * 16 + lg;
#pragma unroll
            for (int ni = 0; ni < 4; ni++) {
                int n = n0 + wn + ni * 8 + 2 * lt;
                float b0 = bias[(size_t)e * NDIM + n];
                float b1v = bias[(size_t)e * NDIM + n + 1];
#pragma unroll
                for (int half = 0; half < 2; half++) {
                    int mm = m + half * 8;
                    float v0 = acc[mi][ni][half * 2 + 0] + b0;
                    float v1 = acc[mi][ni][half * 2 + 1] + b1v;
                    v0 = 0.5f * v0 * (1.0f + erff(v0 * 0.70710678118654752f));
                    v1 = 0.5f * v1 * (1.0f + erff(v1 * 0.70710678118654752f));
                    float2 v = make_float2(to_tf32(v0), to_tf32(v1));
                    *(float2*)(out + ((size_t)e * K_CAP + mm) * F_DIM + n) = v;
                }
            }
        }
    } else {
#pragma unroll
        for (int mi = 0; mi < 4; mi++) {
            int m = m0 + wm + mi * 16 + lg;
            int tok0 = g_sel[e * K_CAP + m];
            int tok1 = g_sel[e * K_CAP + m + 8];
            float w0 = g_wts[e * K_CAP + m];
            float w1v = g_wts[e * K_CAP + m + 8];
#pragma unroll
            for (int ni = 0; ni < 4; ni++) {
                int n = n0 + wn + ni * 8 + 2 * lt;
                float b0 = bias[(size_t)e * NDIM + n];
                float b1v = bias[(size_t)e * NDIM + n + 1];
                atomicAdd(out + (size_t)tok0 * D_DIM + n,     (acc[mi][ni][0] + b0) * w0);
                atomicAdd(out + (size_t)tok0 * D_DIM + n + 1, (acc[mi][ni][1] + b1v) * w0);
                atomicAdd(out + (size_t)tok1 * D_DIM + n,     (acc[mi][ni][2] + b0) * w1v);
                atomicAdd(out + (size_t)tok1 * D_DIM + n + 1, (acc[mi][ni][3] + b1v) * w1v);
            }
        }
    }
}

// ============================================================
// K5: optional extra outputs
// ============================================================
__global__ void tail_kernel(float* __restrict__ out, int mode) {
    int i = blockIdx.x * 256 + threadIdx.x;
    const int R = N_TOK * D_DIM;
    if (mode >= 1 && i < N_TOK * E_NUM) out[R + i] = g_logits[i];
    if (mode >= 2 && i < E_NUM * K_CAP) out[R + N_TOK * E_NUM + i] = (float)g_sel[i];
}

extern "C" void kernel_launch(void* const* d_in, const int* in_sizes, int n_in,
                              void* d_out, int out_size) {
    const float* x  = (const float*)d_in[0];
    const float* rw = (const float*)d_in[1];
    const float* w1 = (const float*)d_in[2];
    const float* b1 = (const float*)d_in[3];
    const float* w2 = (const float*)d_in[4];
    const float* b2 = (const float*)d_in[5];
    float* out = (float*)d_out;

    cudaMemsetAsync(out, 0, (size_t)N_TOK * D_DIM * sizeof(float), 0);

    float *xr, *w1r, *w2r, *h;
    cudaGetSymbolAddress((void**)&xr,  g_xr);
    cudaGetSymbolAddress((void**)&w1r, g_w1r);
    cudaGetSymbolAddress((void**)&w2r, g_w2r);
    cudaGetSymbolAddress((void**)&h,   g_h);

    // staging: tf32-round x, w1, w2 (elementwise, no transpose)
    cvt_round_kernel<<<2048, 256>>>(x,  xr,  (size_t)N_TOK * D_DIM / 4);
    cvt_round_kernel<<<8192, 256>>>(w1, w1r, (size_t)E_NUM * D_DIM * F_DIM / 4);
    cvt_round_kernel<<<8192, 256>>>(w2, w2r, (size_t)E_NUM * F_DIM * D_DIM / 4);

    router_kernel<<<N_TOK, 256>>>(x, rw);

    cudaFuncSetAttribute(topk_select_kernel, cudaFuncAttributeMaxDynamicSharedMemorySize,
                         N_TOK * sizeof(unsigned long long));
    topk_select_kernel<<<E_NUM, 1024, N_TOK * sizeof(unsigned long long)>>>();

    cudaFuncSetAttribute((const void*)moe_gemm_kernel<D_DIM, F_DIM, true>,
                         cudaFuncAttributeMaxDynamicSharedMemorySize, SMEM_DYN);
    cudaFuncSetAttribute((const void*)moe_gemm_kernel<F_DIM, D_DIM, false>,
                         cudaFuncAttributeMaxDynamicSharedMemorySize, SMEM_DYN);

    // GEMM1: h = tf32round(gelu(gather(xr) @ w1r + b1))
    moe_gemm_kernel<D_DIM, F_DIM, true>
        <<<dim3(F_DIM / 128, K_CAP / 128, E_NUM), 256, SMEM_DYN>>>(xr, w1r, b1, h);
    // GEMM2: out += scatter((h @ w2r + b2) * wts)
    moe_gemm_kernel<F_DIM, D_DIM, false>
        <<<dim3(D_DIM / 128, K_CAP / 128, E_NUM), 256, SMEM_DYN>>>(h, w2r, b2, out);

    const int R = N_TOK * D_DIM;
    if (out_size >= R + N_TOK * E_NUM) {
        int mode = (out_size >= R + N_TOK * E_NUM + E_NUM * K_CAP) ? 2 : 1;
        tail_kernel<<<(N_TOK * E_NUM + 255) / 256, 256>>>(out, mode);
    }
}

// round 10
// speedup vs baseline: 3.1733x; 1.0191x over previous
#include <cuda_runtime.h>
#include <math.h>
#include <stdint.h>

#define N_TOK 8192
#define D_DIM 1024
#define E_NUM 8
#define F_DIM 4096
#define K_CAP 1024

// ---- scratch (device globals: no allocation allowed) ----
__device__ float g_logits[N_TOK * E_NUM];
__device__ float g_probsT[E_NUM * N_TOK];
__device__ int   g_sel[E_NUM * K_CAP];
__device__ float g_wts[E_NUM * K_CAP];
__device__ float g_h  [(size_t)E_NUM * K_CAP * F_DIM];   // 128 MB (tf32-rounded)
__device__ float g_xr [(size_t)N_TOK * D_DIM];           // 32 MB
__device__ float g_w1r[(size_t)E_NUM * D_DIM * F_DIM];   // 128 MB
__device__ float g_w2r[(size_t)E_NUM * F_DIM * D_DIM];   // 128 MB

// ============================================================ helpers
__device__ __forceinline__ void cp16(uint32_t dst, const void* src) {
    asm volatile("cp.async.cg.shared.global [%0], [%1], 16;" :: "r"(dst), "l"(src));
}
__device__ __forceinline__ uint32_t smem_u32(const void* p) {
    uint32_t a;
    asm("{ .reg .u64 t; cvta.to.shared.u64 t, %1; cvt.u32.u64 %0, t; }"
        : "=r"(a) : "l"(p));
    return a;
}
__device__ __forceinline__ float to_tf32(float f) {
    float r; asm("cvt.rna.tf32.f32 %0, %1;" : "=f"(r) : "f"(f)); return r;
}
__device__ __forceinline__ void mma1688(float* c, const uint32_t* a, const uint32_t* b) {
    asm volatile(
        "mma.sync.aligned.m16n8k8.row.col.f32.tf32.tf32.f32 "
        "{%0,%1,%2,%3}, {%4,%5,%6,%7}, {%8,%9}, {%0,%1,%2,%3};"
        : "+f"(c[0]), "+f"(c[1]), "+f"(c[2]), "+f"(c[3])
        : "r"(a[0]), "r"(a[1]), "r"(a[2]), "r"(a[3]), "r"(b[0]), "r"(b[1]));
}

// ============================================================
// K0: elementwise tf32 rounding (grid-stride float4)
// ============================================================
__global__ void cvt_round_kernel(const float* __restrict__ src,
                                 float* __restrict__ dst, size_t n4) {
    size_t stride = (size_t)gridDim.x * blockDim.x;
    for (size_t i = (size_t)blockIdx.x * blockDim.x + threadIdx.x; i < n4; i += stride) {
        float4 v = ((const float4*)src)[i];
        v.x = to_tf32(v.x); v.y = to_tf32(v.y);
        v.z = to_tf32(v.z); v.w = to_tf32(v.w);
        ((float4*)dst)[i] = v;
    }
}

// ============================================================
// K1: router logits + softmax. One block per token, float4 single pass.
// ============================================================
__global__ void router_kernel(const float* __restrict__ x,
                              const float* __restrict__ rw) {
    int t = blockIdx.x;
    int tid = threadIdx.x;
    float4 xv = ((const float4*)(x + (size_t)t * D_DIM))[tid];
    float acc[E_NUM];
#pragma unroll
    for (int e = 0; e < E_NUM; e++) {
        float4 wv = ((const float4*)(rw + (size_t)e * D_DIM))[tid];
        float s = xv.x * wv.x;
        s = fmaf(xv.y, wv.y, s);
        s = fmaf(xv.z, wv.z, s);
        acc[e] = fmaf(xv.w, wv.w, s);
    }
    __shared__ float red[E_NUM * 256];
#pragma unroll
    for (int e = 0; e < E_NUM; e++) red[e * 256 + tid] = acc[e];
    __syncthreads();
    for (int s = 128; s > 0; s >>= 1) {
        if (tid < s) {
#pragma unroll
            for (int e = 0; e < E_NUM; e++)
                red[e * 256 + tid] += red[e * 256 + tid + s];
        }
        __syncthreads();
    }
    if (tid == 0) {
        float l[E_NUM];
        float mx = -1e30f;
#pragma unroll
        for (int e = 0; e < E_NUM; e++) {
            l[e] = red[e * 256];
            g_logits[t * E_NUM + e] = l[e];
            mx = fmaxf(mx, l[e]);
        }
        float s = 0.0f;
#pragma unroll
        for (int e = 0; e < E_NUM; e++) { l[e] = expf(l[e] - mx); s += l[e]; }
        float inv = 1.0f / s;
#pragma unroll
        for (int e = 0; e < E_NUM; e++)
            g_probsT[e * N_TOK + t] = l[e] * inv;
    }
}

// ============================================================
// K2: per-expert top-K via radix-select + small bitonic of winners.
// ============================================================
#define TOPK_BINS 4096
__global__ void topk_select_kernel() {
    extern __shared__ unsigned long long cand[];
    __shared__ unsigned hist[TOPK_BINS];
    __shared__ unsigned suf[1024];
    __shared__ unsigned long long outk[K_CAP];
    __shared__ unsigned s_binB, s_need, s_ncand, s_slot, s_coarse;

    int e = blockIdx.x, tid = threadIdx.x;
    const float* p = g_probsT + (size_t)e * N_TOK;

#pragma unroll
    for (int i = 0; i < TOPK_BINS / 1024; i++) hist[tid + i * 1024] = 0;
    if (tid == 0) { s_ncand = 0; s_slot = 0; s_coarse = 0; }
    __syncthreads();

    unsigned fb[8];
#pragma unroll
    for (int k = 0; k < 8; k++) {
        int i = tid + k * 1024;
        fb[k] = __float_as_uint(p[i]);
        atomicAdd(&hist[fb[k] >> 20], 1u);
    }
    __syncthreads();

    unsigned s = hist[4 * tid] + hist[4 * tid + 1] + hist[4 * tid + 2] + hist[4 * tid + 3];
    suf[tid] = s;
    __syncthreads();
    for (int off = 1; off < 1024; off <<= 1) {
        unsigned v = (tid + off < 1024) ? suf[tid + off] : 0;
        __syncthreads();
        suf[tid] += v;
        __syncthreads();
    }
    if (suf[tid] >= K_CAP && (tid == 1023 || suf[tid + 1] < K_CAP)) s_coarse = tid;
    __syncthreads();
    if (tid == 0) {
        unsigned co = s_coarse;
        unsigned above = (co == 1023) ? 0 : suf[co + 1];
        unsigned B = 4 * co, need = 0;
        for (int b = 4 * (int)co + 3; b >= 4 * (int)co; b--) {
            if (above + hist[b] >= K_CAP) { B = (unsigned)b; need = K_CAP - above; break; }
            above += hist[b];
        }
        s_binB = B; s_need = need;
    }
    __syncthreads();
    unsigned B = s_binB, need = s_need;

#pragma unroll
    for (int k = 0; k < 8; k++) {
        int i = tid + k * 1024;
        unsigned b = fb[k] >> 20;
        unsigned long long key =
            ((unsigned long long)fb[k] << 32) | (unsigned)(0xFFFFFFFFu - (unsigned)i);
        if (b > B) {
            unsigned sl = atomicAdd(&s_slot, 1u);
            outk[sl] = key;
        } else if (b == B) {
            unsigned c = atomicAdd(&s_ncand, 1u);
            cand[c] = key;
        }
    }
    __syncthreads();
    unsigned c = s_ncand;
    for (unsigned j = tid; j < c; j += 1024) {
        unsigned long long kj = cand[j];
        unsigned rank = 0;
        for (unsigned l = 0; l < c; l++) rank += (cand[l] > kj);
        if (rank < need) {
            unsigned sl = atomicAdd(&s_slot, 1u);
            outk[sl] = kj;
        }
    }
    __syncthreads();

    for (int k = 2; k <= K_CAP; k <<= 1) {
        for (int j = k >> 1; j > 0; j >>= 1) {
            int ixj = tid ^ j;
            if (ixj > tid) {
                unsigned long long a = outk[tid], bk = outk[ixj];
                bool desc = ((tid & k) == 0);
                if (desc ? (a < bk) : (a > bk)) { outk[tid] = bk; outk[ixj] = a; }
            }
            __syncthreads();
        }
    }
    unsigned long long a = outk[tid];
    g_wts[e * K_CAP + tid] = __uint_as_float((unsigned)(a >> 32));
    g_sel[e * K_CAP + tid] = (int)(0xFFFFFFFFu - (unsigned)(a & 0xFFFFFFFFu));
}

// ============================================================
// tf32 mma.sync GEMM: CTA 128x128, 4 warps (2x2), warp tile 64x64,
// k-tile 16, 5-stage cp.async pipeline. 1.0 LDS per MMA.
// ============================================================
#define A_STRIDE 20
#define B_STRIDE 136
#define A_SZ (128 * A_STRIDE * 4)        // 10240 B
#define B_SZ (16 * B_STRIDE * 4)         // 8704 B
#define STG_SZ (A_SZ + B_SZ)             // 18944 B
#define NSTAGE 5
#define SMEM_DYN (NSTAGE * STG_SZ)       // 94720 B

template <int KDIM, int NDIM, bool IS_G1>
__global__ __launch_bounds__(128, 2) void moe_gemm_kernel(
    const float* __restrict__ A_src, const float* __restrict__ B_src,
    const float* __restrict__ bias, float* __restrict__ out) {
    constexpr int KT = KDIM / 16;

    extern __shared__ char smem[];
    uint32_t sb = smem_u32(smem);
    const uint32_t* smu = (const uint32_t*)smem;

    int e = blockIdx.z, m0 = blockIdx.y * 128, n0 = blockIdx.x * 128;
    int t = threadIdx.x, wid = t >> 5, lane = t & 31;
    int wm = (wid >> 1) * 64, wn = (wid & 1) * 64;

    // cp.async: A 128x16 (512 chunks), B 16x128 (512 chunks), 8 per thread
    int rA = t >> 2, kcA = t & 3;          // A rows rA+32i
    int krB = t >> 5, ncB = t & 31;        // B k-rows krB+4j
    const float* aptr[4];
#pragma unroll
    for (int i = 0; i < 4; i++) {
        int r = rA + 32 * i;
        size_t row;
        if (IS_G1) row = (size_t)g_sel[e * K_CAP + m0 + r];
        else       row = (size_t)e * K_CAP + m0 + r;
        aptr[i] = A_src + row * KDIM + kcA * 4;
    }
    const float* bptr[4];
#pragma unroll
    for (int j = 0; j < 4; j++)
        bptr[j] = B_src + (size_t)e * KDIM * NDIM + (size_t)(krB + 4 * j) * NDIM + n0 + ncB * 4;
    uint32_t adst[4], bdst[4];
#pragma unroll
    for (int i = 0; i < 4; i++)
        adst[i] = sb + (uint32_t)(rA + 32 * i) * (A_STRIDE * 4) + kcA * 16;
#pragma unroll
    for (int j = 0; j < 4; j++)
        bdst[j] = sb + A_SZ + (uint32_t)(krB + 4 * j) * (B_STRIDE * 4) + ncB * 16;

#define LOAD_STAGE(SLOT, KTILE)                                                 \
    do {                                                                        \
        uint32_t off = (uint32_t)(SLOT) * STG_SZ;                               \
        size_t ka = (size_t)(KTILE) * 16;                                       \
        size_t kb = (size_t)(KTILE) * 16 * NDIM;                                \
        _Pragma("unroll")                                                       \
        for (int i = 0; i < 4; i++) cp16(adst[i] + off, aptr[i] + ka);          \
        _Pragma("unroll")                                                       \
        for (int j = 0; j < 4; j++) cp16(bdst[j] + off, bptr[j] + kb);          \
        asm volatile("cp.async.commit_group;");                                 \
    } while (0)

    float acc[4][8][4];
#pragma unroll
    for (int mi = 0; mi < 4; mi++)
#pragma unroll
        for (int ni = 0; ni < 8; ni++)
#pragma unroll
            for (int r = 0; r < 4; r++) acc[mi][ni][r] = 0.0f;

    LOAD_STAGE(0, 0); LOAD_STAGE(1, 1); LOAD_STAGE(2, 2); LOAD_STAGE(3, 3);

    int lg = lane >> 2, lt = lane & 3;
    int cur = 0, nxt = NSTAGE - 1;

#pragma unroll 1
    for (int kt = 0; kt < KT; kt++) {
        int rem = KT - 1 - kt;
        if (rem >= 3)      asm volatile("cp.async.wait_group 3;");
        else if (rem == 2) asm volatile("cp.async.wait_group 2;");
        else if (rem == 1) asm volatile("cp.async.wait_group 1;");
        else               asm volatile("cp.async.wait_group 0;");
        __syncthreads();
        if (kt + NSTAGE - 1 < KT) LOAD_STAGE(nxt, kt + NSTAGE - 1);

        const uint32_t* As = smu + (size_t)cur * (STG_SZ / 4);
        const uint32_t* Bs = As + A_SZ / 4;

#pragma unroll
        for (int s8 = 0; s8 < 2; s8++) {
            int kk = s8 * 8 + lt;
            uint32_t af[4][4], bf[8][2];
#pragma unroll
            for (int mi = 0; mi < 4; mi++) {
                int row = wm + mi * 16 + lg;
                af[mi][0] = As[row * A_STRIDE + kk];
                af[mi][1] = As[(row + 8) * A_STRIDE + kk];
                af[mi][2] = As[row * A_STRIDE + kk + 4];
                af[mi][3] = As[(row + 8) * A_STRIDE + kk + 4];
            }
#pragma unroll
            for (int ni = 0; ni < 8; ni++) {
                int col = wn + ni * 8 + lg;
                bf[ni][0] = Bs[kk * B_STRIDE + col];
                bf[ni][1] = Bs[(kk + 4) * B_STRIDE + col];
            }
#pragma unroll
            for (int mi = 0; mi < 4; mi++)
#pragma unroll
                for (int ni = 0; ni < 8; ni++)
                    mma1688(acc[mi][ni], af[mi], bf[ni]);
        }
        cur = (cur + 1 == NSTAGE) ? 0 : cur + 1;
        nxt = (nxt + 1 == NSTAGE) ? 0 : nxt + 1;
    }
#undef LOAD_STAGE

    // ---- epilogue ----
    if (IS_G1) {
#pragma unroll
        for (int mi = 0; mi < 4; mi++) {
            int m = m0 + wm + mi * 16 + lg;
#pragma unroll
            for (int ni = 0; ni < 8; ni++) {
                int n = n0 + wn + ni * 8 + 2 * lt;
                float b0 = bias[(size_t)e * NDIM + n];
                float b1v = bias[(size_t)e * NDIM + n + 1];
#pragma unroll
                for (int half = 0; half < 2; half++) {
                    int mm = m + half * 8;
                    float v0 = acc[mi][ni][half * 2 + 0] + b0;
                    float v1 = acc[mi][ni][half * 2 + 1] + b1v;
                    v0 = 0.5f * v0 * (1.0f + erff(v0 * 0.70710678118654752f));
                    v1 = 0.5f * v1 * (1.0f + erff(v1 * 0.70710678118654752f));
                    float2 v = make_float2(to_tf32(v0), to_tf32(v1));
                    *(float2*)(out + ((size_t)e * K_CAP + mm) * F_DIM + n) = v;
                }
            }
        }
    } else {
#pragma unroll
        for (int mi = 0; mi < 4; mi++) {
            int m = m0 + wm + mi * 16 + lg;
            int tok0 = g_sel[e * K_CAP + m];
            int tok1 = g_sel[e * K_CAP + m + 8];
            float w0 = g_wts[e * K_CAP + m];
            float w1v = g_wts[e * K_CAP + m + 8];
#pragma unroll
            for (int ni = 0; ni < 8; ni++) {
                int n = n0 + wn + ni * 8 + 2 * lt;
                float b0 = bias[(size_t)e * NDIM + n];
                float b1v = bias[(size_t)e * NDIM + n + 1];
                atomicAdd(out + (size_t)tok0 * D_DIM + n,     (acc[mi][ni][0] + b0) * w0);
                atomicAdd(out + (size_t)tok0 * D_DIM + n + 1, (acc[mi][ni][1] + b1v) * w0);
                atomicAdd(out + (size_t)tok1 * D_DIM + n,     (acc[mi][ni][2] + b0) * w1v);
                atomicAdd(out + (size_t)tok1 * D_DIM + n + 1, (acc[mi][ni][3] + b1v) * w1v);
            }
        }
    }
}

// ============================================================
// K5: optional extra outputs
// ============================================================
__global__ void tail_kernel(float* __restrict__ out, int mode) {
    int i = blockIdx.x * 256 + threadIdx.x;
    const int R = N_TOK * D_DIM;
    if (mode >= 1 && i < N_TOK * E_NUM) out[R + i] = g_logits[i];
    if (mode >= 2 && i < E_NUM * K_CAP) out[R + N_TOK * E_NUM + i] = (float)g_sel[i];
}

extern "C" void kernel_launch(void* const* d_in, const int* in_sizes, int n_in,
                              void* d_out, int out_size) {
    const float* x  = (const float*)d_in[0];
    const float* rw = (const float*)d_in[1];
    const float* w1 = (const float*)d_in[2];
    const float* b1 = (const float*)d_in[3];
    const float* w2 = (const float*)d_in[4];
    const float* b2 = (const float*)d_in[5];
    float* out = (float*)d_out;

    cudaMemsetAsync(out, 0, (size_t)N_TOK * D_DIM * sizeof(float), 0);

    float *xr, *w1r, *w2r, *h;
    cudaGetSymbolAddress((void**)&xr,  g_xr);
    cudaGetSymbolAddress((void**)&w1r, g_w1r);
    cudaGetSymbolAddress((void**)&w2r, g_w2r);
    cudaGetSymbolAddress((void**)&h,   g_h);

    // staging: tf32-round x, w1, w2 (elementwise, no transpose)
    cvt_round_kernel<<<2048, 256>>>(x,  xr,  (size_t)N_TOK * D_DIM / 4);
    cvt_round_kernel<<<8192, 256>>>(w1, w1r, (size_t)E_NUM * D_DIM * F_DIM / 4);
    cvt_round_kernel<<<8192, 256>>>(w2, w2r, (size_t)E_NUM * F_DIM * D_DIM / 4);

    router_kernel<<<N_TOK, 256>>>(x, rw);

    cudaFuncSetAttribute(topk_select_kernel, cudaFuncAttributeMaxDynamicSharedMemorySize,
                         N_TOK * sizeof(unsigned long long));
    topk_select_kernel<<<E_NUM, 1024, N_TOK * sizeof(unsigned long long)>>>();

    cudaFuncSetAttribute((const void*)moe_gemm_kernel<D_DIM, F_DIM, true>,
                         cudaFuncAttributeMaxDynamicSharedMemorySize, SMEM_DYN);
    cudaFuncSetAttribute((const void*)moe_gemm_kernel<F_DIM, D_DIM, false>,
                         cudaFuncAttributeMaxDynamicSharedMemorySize, SMEM_DYN);

    // GEMM1: h = tf32round(gelu(gather(xr) @ w1r + b1))
    moe_gemm_kernel<D_DIM, F_DIM, true>
        <<<dim3(F_DIM / 128, K_CAP / 128, E_NUM), 128, SMEM_DYN>>>(xr, w1r, b1, h);
    // GEMM2: out += scatter((h @ w2r + b2) * wts)
    moe_gemm_kernel<F_DIM, D_DIM, false>
        <<<dim3(D_DIM / 128, K_CAP / 128, E_NUM), 128, SMEM_DYN>>>(h, w2r, b2, out);

    const int R = N_TOK * D_DIM;
    if (out_size >= R + N_TOK * E_NUM) {
        int mode = (out_size >= R + N_TOK * E_NUM + E_NUM * K_CAP) ? 2 : 1;
        tail_kernel<<<(N_TOK * E_NUM + 255) / 256, 256>>>(out, mode);
    }
}